// round 12
// baseline (speedup 1.0000x reference)
#include <cuda_runtime.h>
#include <cuda_fp8.h>
#include <cstdint>

#define DIM 2048
#define NB  (DIM / 32)   // 64 scale blocks per row

// ---------------- scratch (device globals: no allocation allowed) ----------------
__device__ uint8_t g_xq[DIM * DIM];   // x quantized e4m3
__device__ uint8_t g_wq[DIM * DIM];   // w quantized e4m3
__device__ float   g_sxT[NB * DIM];   // x block scales, TRANSPOSED [block][row]
__device__ float   g_swT[NB * DIM];   // w block scales, TRANSPOSED [block][row]

// ---------------- quantizer: 8 threads per 32-block, 2 blocks per thread (MLP=2) ----
__global__ void __launch_bounds__(512) quant2_kernel(
        const float* __restrict__ x, const float* __restrict__ w) {
    const int Q = DIM * DIM / 4;                    // float4 count per tensor
    const int gtid = blockIdx.x * blockDim.x + threadIdx.x;   // [0, Q)
    const bool isW = gtid >= Q / 2;
    const int t0 = isW ? gtid - Q / 2 : gtid;       // [0, Q/2)
    const int t1 = t0 + Q / 2;
    const float4* src = reinterpret_cast<const float4*>(isW ? w : x);
    const float4 v0 = src[t0];
    const float4 v1 = src[t1];

    float m0 = fmaxf(fmaxf(fabsf(v0.x), fabsf(v0.y)), fmaxf(fabsf(v0.z), fabsf(v0.w)));
    float m1 = fmaxf(fmaxf(fabsf(v1.x), fabsf(v1.y)), fmaxf(fabsf(v1.z), fabsf(v1.w)));
    m0 = fmaxf(m0, __shfl_xor_sync(0xFFFFFFFFu, m0, 1));
    m1 = fmaxf(m1, __shfl_xor_sync(0xFFFFFFFFu, m1, 1));
    m0 = fmaxf(m0, __shfl_xor_sync(0xFFFFFFFFu, m0, 2));
    m1 = fmaxf(m1, __shfl_xor_sync(0xFFFFFFFFu, m1, 2));
    m0 = fmaxf(m0, __shfl_xor_sync(0xFFFFFFFFu, m0, 4));
    m1 = fmaxf(m1, __shfl_xor_sync(0xFFFFFFFFu, m1, 4));
    const float s0 = fmaxf(__fdiv_rn(m0, 448.0f), 1e-30f);
    const float s1 = fmaxf(__fdiv_rn(m1, 448.0f), 1e-30f);

    uint32_t* dstq = reinterpret_cast<uint32_t*>(isW ? g_wq : g_xq);
    float* dsts = isW ? g_swT : g_sxT;
    const float e0[4] = {v0.x, v0.y, v0.z, v0.w};
    const float e1[4] = {v1.x, v1.y, v1.z, v1.w};
    uint32_t p0 = 0, p1 = 0;
#pragma unroll
    for (int j = 0; j < 4; j++) {
        p0 |= ((uint32_t)(uint8_t)__nv_cvt_float_to_fp8(__fdiv_rn(e0[j], s0),
                __NV_SATFINITE, __NV_E4M3)) << (8 * j);
        p1 |= ((uint32_t)(uint8_t)__nv_cvt_float_to_fp8(__fdiv_rn(e1[j], s1),
                __NV_SATFINITE, __NV_E4M3)) << (8 * j);
    }
    dstq[t0] = p0;
    dstq[t1] = p1;
    if ((t0 & 7) == 0) {
        const int i0 = t0 >> 3, i1 = t1 >> 3;       // row-major block indices
        dsts[(i0 & 63) * DIM + (i0 >> 6)] = s0;
        dsts[(i1 & 63) * DIM + (i1 >> 6)] = s1;
    }
}

// ---------------- GEMM: CTA 64x128, 8 warps of 32x32, 2 CTAs/SM, 3-stage ----------------
// Stage: A 8KB | B 16KB | SX 1KB | SW 2KB = 27648 B; three stages = 82944 B per CTA.
static constexpr int STG      = 27648;
static constexpr int OFF_B    = 8192;
static constexpr int OFF_SX   = 24576;
static constexpr int OFF_SW   = 25600;
static constexpr int SMEM_TOT = 3 * STG;

#define SWZ_OFF(r, c) (((r) * 128) + ((((c) ^ ((r) & 7)) & 7) << 4))

__device__ __forceinline__ void cp16(uint32_t saddr, const void* gptr) {
    asm volatile("cp.async.cg.shared.global [%0], [%1], 16;"
                 :: "r"(saddr), "l"(__cvta_generic_to_global(gptr)));
}
__device__ __forceinline__ void cp16ca(uint32_t saddr, const void* gptr) {
    asm volatile("cp.async.ca.shared.global [%0], [%1], 16;"
                 :: "r"(saddr), "l"(__cvta_generic_to_global(gptr)));
}

// pure register ops — NOT volatile (ptxas may schedule freely; deps carry correctness)
__device__ __forceinline__ unsigned long long pk2(float lo, float hi) {
    unsigned long long r;
    asm("mov.b64 %0, {%1, %2};" : "=l"(r) : "f"(lo), "f"(hi));
    return r;
}
__device__ __forceinline__ unsigned long long mul2(unsigned long long a, unsigned long long b) {
    unsigned long long r;
    asm("mul.rn.f32x2 %0, %1, %2;" : "=l"(r) : "l"(a), "l"(b));
    return r;
}
__device__ __forceinline__ unsigned long long fma2(unsigned long long a, unsigned long long b,
                                                   unsigned long long c) {
    unsigned long long r;
    asm("fma.rn.f32x2 %0, %1, %2, %3;" : "=l"(r) : "l"(a), "l"(b), "l"(c));
    return r;
}
__device__ __forceinline__ void mma_e4m3(float& d0, float& d1, float& d2, float& d3,
                                         const uint32_t a[4], uint32_t b0, uint32_t b1) {
    asm("mma.sync.aligned.m16n8k32.row.col.f32.e4m3.e4m3.f32 "
        "{%0,%1,%2,%3}, {%4,%5,%6,%7}, {%8,%9}, {%10,%11,%12,%13};"
        : "=f"(d0), "=f"(d1), "=f"(d2), "=f"(d3)
        : "r"(a[0]), "r"(a[1]), "r"(a[2]), "r"(a[3]), "r"(b0), "r"(b1),
          "f"(0.f), "f"(0.f), "f"(0.f), "f"(0.f));
}

__global__ void __launch_bounds__(256, 2)
gemm_kernel(const float* __restrict__ bias, float* __restrict__ out) {
    extern __shared__ __align__(1024) char smem[];
    const uint32_t sbase = (uint32_t)__cvta_generic_to_shared(smem);
    const int tid  = threadIdx.x;
    const int lane = tid & 31, warp = tid >> 5;
    const int m0 = blockIdx.y * 64, n0 = blockIdx.x * 128;
    const int wm0 = (warp >> 2) * 32, wn0 = (warp & 3) * 32;   // 2x4 warp grid

    unsigned long long acc[2][4][2] = {};

    // ---- loader: A 64 rows x 8 chunks (2/thread), B 128 rows x 8 chunks (4/thread) ----
    const int ar  = tid >> 2;                       // A row 0..63
    const int ac0 = (tid & 3) * 2;                  // A chunk pair
    const uint32_t aoff0 = SWZ_OFF(ar, ac0);
    const uint32_t aoff1 = SWZ_OFF(ar, ac0 + 1);
    const uint8_t* gA = g_xq + (size_t)(m0 + ar) * DIM + ac0 * 16;
    const int br  = tid >> 1;                       // B row 0..127
    const int bc0 = (tid & 1) * 4;                  // B chunk quad
    uint32_t boff[4];
#pragma unroll
    for (int i = 0; i < 4; i++) boff[i] = OFF_B + SWZ_OFF(br, bc0 + i);
    const uint8_t* gB = g_wq + (size_t)(n0 + br) * DIM + bc0 * 16;

    const float* gS = nullptr;
    uint32_t soff = 0;
    if (tid < 64) {          // SX: [b][row], 256B per b, 64 rows
        gS = g_sxT + (size_t)(tid >> 4) * DIM + m0 + (tid & 15) * 4;
        soff = OFF_SX + tid * 16;
    } else if (tid < 192) {  // SW: [b][row], 512B per b, 128 rows
        const int t = tid - 64;
        gS = g_swT + (size_t)(t >> 5) * DIM + n0 + (t & 31) * 4;
        soff = OFF_SW + t * 16;
    }

    uint32_t woff = 0;
    auto load_stage = [&]() {
        const uint32_t sb = sbase + woff;
        cp16(sb + aoff0, gA);
        cp16(sb + aoff1, gA + 16);
#pragma unroll
        for (int i = 0; i < 4; i++) cp16(sb + boff[i], gB + i * 16);
        gA += 128; gB += 128;
        if (tid < 192) { cp16ca(sb + soff, gS); gS += 4 * DIM; }
        woff = (woff == 2 * STG) ? 0u : woff + STG;
    };

    // ---- fragment base offsets (b enters only as XOR (b<<5)) ----
    const int mlm = lane >> 3;
    const int rA  = wm0 + (lane & 15);
    const uint32_t offA0 = SWZ_OFF(rA, (lane >> 4));
    const uint32_t offA1 = offA0 + 16 * 128;
    const int rB  = wn0 + ((mlm >> 1) << 3) + (lane & 7);
    const uint32_t offB0 = OFF_B + SWZ_OFF(rB, (mlm & 1));
    const uint32_t offB1 = offB0 + 16 * 128;
    const uint32_t offSX = OFF_SX + ((uint32_t)(wm0 + (lane >> 2)) << 2);
    const uint32_t offSW = OFF_SW + ((uint32_t)(wn0 + ((lane & 3) << 1)) << 2);

    load_stage();
    asm volatile("cp.async.commit_group;" ::: "memory");
    load_stage();
    asm volatile("cp.async.commit_group;" ::: "memory");

    uint32_t roff = 0;
#pragma unroll 1
    for (int kc = 0; kc < 16; kc++) {
        asm volatile("cp.async.wait_group 1;" ::: "memory");
        __syncthreads();
        if (kc < 14) load_stage();
        asm volatile("cp.async.commit_group;" ::: "memory");

        const uint32_t sb = sbase + roff;
        const char* ss = smem + roff;
        const uint32_t a0 = sb + offA0, a1 = sb + offA1;
        const uint32_t b0 = sb + offB0, b1 = sb + offB1;
        const char* px = ss + offSX;
        const char* pw = ss + offSW;

#pragma unroll
        for (int b = 0; b < 4; b++) {
            const uint32_t bx = (uint32_t)b << 5;
            uint32_t af[2][4];
            asm volatile("ldmatrix.sync.aligned.m8n8.x4.shared.b16 {%0,%1,%2,%3}, [%4];"
                         : "=r"(af[0][0]), "=r"(af[0][1]), "=r"(af[0][2]), "=r"(af[0][3])
                         : "r"(a0 ^ bx));
            asm volatile("ldmatrix.sync.aligned.m8n8.x4.shared.b16 {%0,%1,%2,%3}, [%4];"
                         : "=r"(af[1][0]), "=r"(af[1][1]), "=r"(af[1][2]), "=r"(af[1][3])
                         : "r"(a1 ^ bx));
            uint32_t bf[4][2];
            asm volatile("ldmatrix.sync.aligned.m8n8.x4.shared.b16 {%0,%1,%2,%3}, [%4];"
                         : "=r"(bf[0][0]), "=r"(bf[0][1]), "=r"(bf[1][0]), "=r"(bf[1][1])
                         : "r"(b0 ^ bx));
            asm volatile("ldmatrix.sync.aligned.m8n8.x4.shared.b16 {%0,%1,%2,%3}, [%4];"
                         : "=r"(bf[2][0]), "=r"(bf[2][1]), "=r"(bf[3][0]), "=r"(bf[3][1])
                         : "r"(b1 ^ bx));

            // scales: b-major smem layout => immediate offsets
            unsigned long long sxaa[2], sxbb[2];
#pragma unroll
            for (int mt = 0; mt < 2; mt++) {
                const float a  = *reinterpret_cast<const float*>(px + b * 256 + mt * 64);
                const float bb = *reinterpret_cast<const float*>(px + b * 256 + mt * 64 + 32);
                sxaa[mt] = pk2(a, a);
                sxbb[mt] = pk2(bb, bb);
            }

#pragma unroll
            for (int nt = 0; nt < 4; nt++) {
                const float2 v2 = *reinterpret_cast<const float2*>(pw + b * 512 + nt * 32);
                const unsigned long long sw01 = pk2(v2.x, v2.y);
                const unsigned long long pA0 = mul2(sxaa[0], sw01);
                const unsigned long long pB0 = mul2(sxbb[0], sw01);
                const unsigned long long pA1 = mul2(sxaa[1], sw01);
                const unsigned long long pB1 = mul2(sxbb[1], sw01);

                float d0, d1, d2, d3, e0, e1, e2, e3;
                mma_e4m3(d0, d1, d2, d3, af[0], bf[nt][0], bf[nt][1]);
                mma_e4m3(e0, e1, e2, e3, af[1], bf[nt][0], bf[nt][1]);
                acc[0][nt][0] = fma2(pA0, pk2(d0, d1), acc[0][nt][0]);
                acc[0][nt][1] = fma2(pB0, pk2(d2, d3), acc[0][nt][1]);
                acc[1][nt][0] = fma2(pA1, pk2(e0, e1), acc[1][nt][0]);
                acc[1][nt][1] = fma2(pB1, pk2(e2, e3), acc[1][nt][1]);
            }
        }
        roff = (roff == 2 * STG) ? 0u : roff + STG;
    }

    // ---- epilogue: add bias, store fp32 ----
#pragma unroll
    for (int mt = 0; mt < 2; mt++) {
        const int r0 = m0 + wm0 + mt * 16 + (lane >> 2);
#pragma unroll
        for (int nt = 0; nt < 4; nt++) {
            const int cj = n0 + wn0 + nt * 8 + ((lane & 3) << 1);
            const float2 bz = *reinterpret_cast<const float2*>(bias + cj);
            const unsigned long long a0 = acc[mt][nt][0], a1 = acc[mt][nt][1];
            float2 o0 = make_float2(__uint_as_float((uint32_t)a0) + bz.x,
                                    __uint_as_float((uint32_t)(a0 >> 32)) + bz.y);
            float2 o1 = make_float2(__uint_as_float((uint32_t)a1) + bz.x,
                                    __uint_as_float((uint32_t)(a1 >> 32)) + bz.y);
            *reinterpret_cast<float2*>(out + (size_t)r0 * DIM + cj) = o0;
            *reinterpret_cast<float2*>(out + (size_t)(r0 + 8) * DIM + cj) = o1;
        }
    }
}

// ---------------- launch ----------------
extern "C" void kernel_launch(void* const* d_in, const int* in_sizes, int n_in,
                              void* d_out, int out_size) {
    const float* x    = (const float*)d_in[0];
    const float* w    = (const float*)d_in[1];
    const float* bias = (const float*)d_in[2];
    float* out = (float*)d_out;

    cudaFuncSetAttribute(gemm_kernel, cudaFuncAttributeMaxDynamicSharedMemorySize, SMEM_TOT);

    const int nthreads = DIM * DIM / 4;             // 2 float4 per thread, both tensors
    quant2_kernel<<<nthreads / 512, 512>>>(x, w);
    gemm_kernel<<<dim3(16, 32), 256, SMEM_TOT>>>(bias, out);
}

// round 13
// speedup vs baseline: 1.0463x; 1.0463x over previous
#include <cuda_runtime.h>
#include <cuda_fp8.h>
#include <cstdint>

#define DIM 2048
#define NB  (DIM / 32)   // 64 scale blocks per row

// ---------------- scratch (device globals: no allocation allowed) ----------------
__device__ uint8_t g_xq[DIM * DIM];   // x quantized e4m3
__device__ uint8_t g_wq[DIM * DIM];   // w quantized e4m3
__device__ float   g_sxT[NB * DIM];   // x block scales, TRANSPOSED [block][row]
__device__ float   g_swT[NB * DIM];   // w block scales, TRANSPOSED [block][row]

// ---------------- quantizer: 8 threads per 32-block, 2 blocks per thread (MLP=2) ----
__global__ void __launch_bounds__(512) quant2_kernel(
        const float* __restrict__ x, const float* __restrict__ w) {
    const int Q = DIM * DIM / 4;                    // float4 count per tensor
    const int gtid = blockIdx.x * blockDim.x + threadIdx.x;   // [0, Q)
    const bool isW = gtid >= Q / 2;
    const int t0 = isW ? gtid - Q / 2 : gtid;       // [0, Q/2)
    const int t1 = t0 + Q / 2;
    const float4* src = reinterpret_cast<const float4*>(isW ? w : x);
    const float4 v0 = src[t0];
    const float4 v1 = src[t1];

    float m0 = fmaxf(fmaxf(fabsf(v0.x), fabsf(v0.y)), fmaxf(fabsf(v0.z), fabsf(v0.w)));
    float m1 = fmaxf(fmaxf(fabsf(v1.x), fabsf(v1.y)), fmaxf(fabsf(v1.z), fabsf(v1.w)));
    m0 = fmaxf(m0, __shfl_xor_sync(0xFFFFFFFFu, m0, 1));
    m1 = fmaxf(m1, __shfl_xor_sync(0xFFFFFFFFu, m1, 1));
    m0 = fmaxf(m0, __shfl_xor_sync(0xFFFFFFFFu, m0, 2));
    m1 = fmaxf(m1, __shfl_xor_sync(0xFFFFFFFFu, m1, 2));
    m0 = fmaxf(m0, __shfl_xor_sync(0xFFFFFFFFu, m0, 4));
    m1 = fmaxf(m1, __shfl_xor_sync(0xFFFFFFFFu, m1, 4));
    const float s0 = fmaxf(__fdiv_rn(m0, 448.0f), 1e-30f);
    const float s1 = fmaxf(__fdiv_rn(m1, 448.0f), 1e-30f);

    uint32_t* dstq = reinterpret_cast<uint32_t*>(isW ? g_wq : g_xq);
    float* dsts = isW ? g_swT : g_sxT;
    const float e0[4] = {v0.x, v0.y, v0.z, v0.w};
    const float e1[4] = {v1.x, v1.y, v1.z, v1.w};
    uint32_t p0 = 0, p1 = 0;
#pragma unroll
    for (int j = 0; j < 4; j++) {
        p0 |= ((uint32_t)(uint8_t)__nv_cvt_float_to_fp8(__fdiv_rn(e0[j], s0),
                __NV_SATFINITE, __NV_E4M3)) << (8 * j);
        p1 |= ((uint32_t)(uint8_t)__nv_cvt_float_to_fp8(__fdiv_rn(e1[j], s1),
                __NV_SATFINITE, __NV_E4M3)) << (8 * j);
    }
    dstq[t0] = p0;
    dstq[t1] = p1;
    if ((t0 & 7) == 0) {
        const int i0 = t0 >> 3, i1 = t1 >> 3;       // row-major block indices
        dsts[(i0 & 63) * DIM + (i0 >> 6)] = s0;
        dsts[(i1 & 63) * DIM + (i1 >> 6)] = s1;
    }
}

// ---------------- GEMM: CTA 128x128, 16 warps of 32x32, 3-stage cp.async (R7) ----------
// Stage: A 16KB | B 16KB | SX 2KB | SW 2KB => 36864 B; three stages = 110592 B.
static constexpr int STG      = 36864;
static constexpr int OFF_B    = 16384;
static constexpr int OFF_SX   = 32768;
static constexpr int OFF_SW   = 34816;
static constexpr int SMEM_TOT = 3 * STG;

#define SWZ_OFF(r, c) (((r) * 128) + ((((c) ^ ((r) & 7)) & 7) << 4))

__device__ __forceinline__ void cp16(uint32_t saddr, const void* gptr) {
    asm volatile("cp.async.cg.shared.global [%0], [%1], 16;"
                 :: "r"(saddr), "l"(__cvta_generic_to_global(gptr)));
}
__device__ __forceinline__ void cp16ca(uint32_t saddr, const void* gptr) {
    asm volatile("cp.async.ca.shared.global [%0], [%1], 16;"
                 :: "r"(saddr), "l"(__cvta_generic_to_global(gptr)));
}

__device__ __forceinline__ unsigned long long pk2(float lo, float hi) {
    unsigned long long r;
    asm("mov.b64 %0, {%1, %2};" : "=l"(r) : "f"(lo), "f"(hi));
    return r;
}
__device__ __forceinline__ unsigned long long mul2(unsigned long long a, unsigned long long b) {
    unsigned long long r;
    asm("mul.rn.f32x2 %0, %1, %2;" : "=l"(r) : "l"(a), "l"(b));
    return r;
}
__device__ __forceinline__ unsigned long long fma2(unsigned long long a, unsigned long long b,
                                                   unsigned long long c) {
    unsigned long long r;
    asm("fma.rn.f32x2 %0, %1, %2, %3;" : "=l"(r) : "l"(a), "l"(b), "l"(c));
    return r;
}

__global__ void __launch_bounds__(512, 1)
gemm_kernel(const float* __restrict__ bias, float* __restrict__ out) {
    extern __shared__ __align__(1024) char smem[];
    const uint32_t sbase = (uint32_t)__cvta_generic_to_shared(smem);
    const int tid  = threadIdx.x;
    const int lane = tid & 31, warp = tid >> 5;
    const int m0 = blockIdx.y * 128, n0 = blockIdx.x * 128;
    const int wm0 = (warp >> 2) * 32, wn0 = (warp & 3) * 32;   // 4x4 warp grid

    unsigned long long acc[2][4][2] = {};

    // ---- loader constants: each thread owns one row-chunk pair (32B contiguous) ----
    const int lr  = tid >> 2;
    const int lc0 = (tid & 3) * 2;
    const uint32_t aoff0 = SWZ_OFF(lr, lc0);
    const uint32_t aoff1 = SWZ_OFF(lr, lc0 + 1);
    const uint8_t* gA = g_xq + (size_t)(m0 + lr) * DIM + lc0 * 16;
    const uint8_t* gB = g_wq + (size_t)(n0 + lr) * DIM + lc0 * 16;
    const float* gS = nullptr;
    uint32_t soff = 0;
    if (tid < 128) {
        gS = g_sxT + (size_t)(tid >> 5) * DIM + m0 + (tid & 31) * 4;
        soff = OFF_SX + tid * 16;
    } else if (tid < 256) {
        const int t = tid - 128;
        gS = g_swT + (size_t)(t >> 5) * DIM + n0 + (t & 31) * 4;
        soff = OFF_SW + t * 16;
    }

    uint32_t woff = 0;
    auto load_stage = [&]() {
        const uint32_t sb = sbase + woff;
        cp16(sb + aoff0, gA);
        cp16(sb + aoff1, gA + 16);
        cp16(sb + OFF_B + aoff0, gB);
        cp16(sb + OFF_B + aoff1, gB + 16);
        gA += 128; gB += 128;
        if (tid < 256) { cp16ca(sb + soff, gS); gS += 4 * DIM; }
        woff = (woff == 2 * STG) ? 0u : woff + STG;
    };

    // ---- fragment base offsets (b enters only as XOR (b<<5)) ----
    const int mlm = lane >> 3;
    const int rA  = wm0 + (lane & 15);
    const uint32_t offA0 = SWZ_OFF(rA, (lane >> 4));
    const uint32_t offA1 = offA0 + 16 * 128;
    const int rB  = wn0 + ((mlm >> 1) << 3) + (lane & 7);
    const uint32_t offB0 = OFF_B + SWZ_OFF(rB, (mlm & 1));
    const uint32_t offB1 = offB0 + 16 * 128;
    const uint32_t offSX = OFF_SX + ((uint32_t)(wm0 + (lane >> 2)) << 2);
    const uint32_t offSW = OFF_SW + ((uint32_t)(wn0 + ((lane & 3) << 1)) << 2);

    load_stage();
    asm volatile("cp.async.commit_group;" ::: "memory");
    load_stage();
    asm volatile("cp.async.commit_group;" ::: "memory");

    uint32_t roff = 0;
#pragma unroll 1
    for (int kc = 0; kc < 16; kc++) {
        asm volatile("cp.async.wait_group 1;" ::: "memory");
        __syncthreads();
        if (kc < 14) load_stage();
        asm volatile("cp.async.commit_group;" ::: "memory");

        const uint32_t sb = sbase + roff;
        const char* ss = smem + roff;
        const uint32_t a0 = sb + offA0, a1 = sb + offA1;
        const uint32_t b0 = sb + offB0, b1 = sb + offB1;
        const char* px = ss + offSX;
        const char* pw = ss + offSW;

#pragma unroll
        for (int b = 0; b < 4; b++) {
            const uint32_t bx = (uint32_t)b << 5;
            uint32_t af[2][4];
            asm volatile("ldmatrix.sync.aligned.m8n8.x4.shared.b16 {%0,%1,%2,%3}, [%4];"
                         : "=r"(af[0][0]), "=r"(af[0][1]), "=r"(af[0][2]), "=r"(af[0][3])
                         : "r"(a0 ^ bx));
            asm volatile("ldmatrix.sync.aligned.m8n8.x4.shared.b16 {%0,%1,%2,%3}, [%4];"
                         : "=r"(af[1][0]), "=r"(af[1][1]), "=r"(af[1][2]), "=r"(af[1][3])
                         : "r"(a1 ^ bx));
            uint32_t bf[4][2];
            asm volatile("ldmatrix.sync.aligned.m8n8.x4.shared.b16 {%0,%1,%2,%3}, [%4];"
                         : "=r"(bf[0][0]), "=r"(bf[0][1]), "=r"(bf[1][0]), "=r"(bf[1][1])
                         : "r"(b0 ^ bx));
            asm volatile("ldmatrix.sync.aligned.m8n8.x4.shared.b16 {%0,%1,%2,%3}, [%4];"
                         : "=r"(bf[2][0]), "=r"(bf[2][1]), "=r"(bf[3][0]), "=r"(bf[3][1])
                         : "r"(b1 ^ bx));

            // scales: b-major smem layout => all offsets are immediates
            unsigned long long sxaa[2], sxbb[2];
#pragma unroll
            for (int mt = 0; mt < 2; mt++) {
                const float a  = *reinterpret_cast<const float*>(px + b * 512 + mt * 64);
                const float bb = *reinterpret_cast<const float*>(px + b * 512 + mt * 64 + 32);
                sxaa[mt] = pk2(a, a);
                sxbb[mt] = pk2(bb, bb);
            }

#pragma unroll
            for (int nt = 0; nt < 4; nt++) {
                const float2 v2 = *reinterpret_cast<const float2*>(pw + b * 512 + nt * 32);
                const unsigned long long sw01 = pk2(v2.x, v2.y);
                const unsigned long long pA0 = mul2(sxaa[0], sw01);
                const unsigned long long pB0 = mul2(sxbb[0], sw01);
                const unsigned long long pA1 = mul2(sxaa[1], sw01);
                const unsigned long long pB1 = mul2(sxbb[1], sw01);

                float d0, d1, d2, d3, e0, e1, e2, e3;
                asm volatile(
                    "mma.sync.aligned.m16n8k32.row.col.f32.e4m3.e4m3.f32 "
                    "{%0,%1,%2,%3}, {%4,%5,%6,%7}, {%8,%9}, {%10,%11,%12,%13};"
                    : "=f"(d0), "=f"(d1), "=f"(d2), "=f"(d3)
                    : "r"(af[0][0]), "r"(af[0][1]), "r"(af[0][2]), "r"(af[0][3]),
                      "r"(bf[nt][0]), "r"(bf[nt][1]),
                      "f"(0.f), "f"(0.f), "f"(0.f), "f"(0.f));
                asm volatile(
                    "mma.sync.aligned.m16n8k32.row.col.f32.e4m3.e4m3.f32 "
                    "{%0,%1,%2,%3}, {%4,%5,%6,%7}, {%8,%9}, {%10,%11,%12,%13};"
                    : "=f"(e0), "=f"(e1), "=f"(e2), "=f"(e3)
                    : "r"(af[1][0]), "r"(af[1][1]), "r"(af[1][2]), "r"(af[1][3]),
                      "r"(bf[nt][0]), "r"(bf[nt][1]),
                      "f"(0.f), "f"(0.f), "f"(0.f), "f"(0.f));
                acc[0][nt][0] = fma2(pA0, pk2(d0, d1), acc[0][nt][0]);
                acc[0][nt][1] = fma2(pB0, pk2(d2, d3), acc[0][nt][1]);
                acc[1][nt][0] = fma2(pA1, pk2(e0, e1), acc[1][nt][0]);
                acc[1][nt][1] = fma2(pB1, pk2(e2, e3), acc[1][nt][1]);
            }
        }
        roff = (roff == 2 * STG) ? 0u : roff + STG;
    }

    // ---- epilogue: add bias, store fp32 ----
#pragma unroll
    for (int mt = 0; mt < 2; mt++) {
        const int r0 = m0 + wm0 + mt * 16 + (lane >> 2);
#pragma unroll
        for (int nt = 0; nt < 4; nt++) {
            const int cj = n0 + wn0 + nt * 8 + ((lane & 3) << 1);
            const float2 bz = *reinterpret_cast<const float2*>(bias + cj);
            const unsigned long long a0 = acc[mt][nt][0], a1 = acc[mt][nt][1];
            float2 o0 = make_float2(__uint_as_float((uint32_t)a0) + bz.x,
                                    __uint_as_float((uint32_t)(a0 >> 32)) + bz.y);
            float2 o1 = make_float2(__uint_as_float((uint32_t)a1) + bz.x,
                                    __uint_as_float((uint32_t)(a1 >> 32)) + bz.y);
            *reinterpret_cast<float2*>(out + (size_t)r0 * DIM + cj) = o0;
            *reinterpret_cast<float2*>(out + (size_t)(r0 + 8) * DIM + cj) = o1;
        }
    }
}

// ---------------- launch ----------------
extern "C" void kernel_launch(void* const* d_in, const int* in_sizes, int n_in,
                              void* d_out, int out_size) {
    const float* x    = (const float*)d_in[0];
    const float* w    = (const float*)d_in[1];
    const float* bias = (const float*)d_in[2];
    float* out = (float*)d_out;

    cudaFuncSetAttribute(gemm_kernel, cudaFuncAttributeMaxDynamicSharedMemorySize, SMEM_TOT);

    const int nthreads = DIM * DIM / 4;             // 2 float4 per thread, both tensors
    quant2_kernel<<<nthreads / 512, 512>>>(x, w);
    gemm_kernel<<<dim3(16, 16), 512, SMEM_TOT>>>(bias, out);
}